// round 11
// baseline (speedup 1.0000x reference)
#include <cuda_runtime.h>
#include <math_constants.h>
#include <stdint.h>

// N=4096 mention-ranking loss, row-paired CTAs {b, 4095-b}, one streaming pass.
// R3 skeleton (best: 12.77us). Delta: mask loads are aligned v8 (LDG.256) with
// L2::evict_last so the 33.5MB mask stream can stay L2-resident across graph
// replays (working set fits; plain LRU self-evicts cyclically). ana stays
// scalar __ldg (unaligned rows; proven fastest variant for that stream).

#define NMENT 4096
#define BLOCK 128

struct F8 { float f[8]; };

__device__ __forceinline__ F8 ldg_el8(const float* p)
{
    uint32_t a0,a1,a2,a3,a4,a5,a6,a7;
    asm("ld.global.nc.L2::evict_last.v8.b32 {%0,%1,%2,%3,%4,%5,%6,%7}, [%8];"
        : "=r"(a0),"=r"(a1),"=r"(a2),"=r"(a3),
          "=r"(a4),"=r"(a5),"=r"(a6),"=r"(a7) : "l"(p));
    F8 r;
    r.f[0]=__uint_as_float(a0); r.f[1]=__uint_as_float(a1);
    r.f[2]=__uint_as_float(a2); r.f[3]=__uint_as_float(a3);
    r.f[4]=__uint_as_float(a4); r.f[5]=__uint_as_float(a5);
    r.f[6]=__uint_as_float(a6); r.f[7]=__uint_as_float(a7);
    return r;
}

__device__ __forceinline__ void acc_one(float m, float s, float& bestM, float& maxU)
{
    if (m > 0.5f) bestM = fmaxf(bestM, s);
    else          maxU  = fmaxf(maxU,  s);
}

__global__ __launch_bounds__(BLOCK, 12)
void mention_loss_kernel(const float* __restrict__ eps_scores,
                         const float* __restrict__ ana_scores,
                         const float* __restrict__ mask,
                         const float* __restrict__ link_costs,
                         const float* __restrict__ false_new_cost,
                         float* __restrict__ out)
{
    const int b    = (int)blockIdx.x;        // 0..2047
    const int tid  = (int)threadIdx.x;
    const int warp = tid >> 5;
    const int lane = tid & 31;

    __shared__ float sM[2][BLOCK / 32];
    __shared__ float sU[2][BLOCK / 32];

    const float lc0 = __ldg(link_costs + 0);    // false_link
    const float lc1 = __ldg(link_costs + 1);    // wrong_link
    const float fnc = __ldg(false_new_cost);

    #pragma unroll
    for (int r = 0; r < 2; ++r) {
        const int row = (r == 0) ? b : (NMENT - 1 - b);

        const float* __restrict__ mrow = mask + (size_t)row * NMENT;   // 32B-aligned
        const long long abase = ((long long)row * (row - 1)) >> 1;
        const float* __restrict__ arow = ana_scores + abase;

        float bestM = -CUDART_INF_F;
        float maxU  = -CUDART_INF_F;

        const int nv = row >> 3;               // full 8-element groups

        for (int v = tid; v < nv; v += BLOCK) {
            const int j0 = v << 3;
            const F8 m = ldg_el8(mrow + j0);   // evict_last: resident stream
            const float s0 = __ldg(arow + j0 + 0);
            const float s1 = __ldg(arow + j0 + 1);
            const float s2 = __ldg(arow + j0 + 2);
            const float s3 = __ldg(arow + j0 + 3);
            const float s4 = __ldg(arow + j0 + 4);
            const float s5 = __ldg(arow + j0 + 5);
            const float s6 = __ldg(arow + j0 + 6);
            const float s7 = __ldg(arow + j0 + 7);
            acc_one(m.f[0], s0, bestM, maxU);
            acc_one(m.f[1], s1, bestM, maxU);
            acc_one(m.f[2], s2, bestM, maxU);
            acc_one(m.f[3], s3, bestM, maxU);
            acc_one(m.f[4], s4, bestM, maxU);
            acc_one(m.f[5], s5, bestM, maxU);
            acc_one(m.f[6], s6, bestM, maxU);
            acc_one(m.f[7], s7, bestM, maxU);
        }
        // Scalar tail: j in [nv*8, row)
        for (int j = (nv << 3) + tid; j < row; j += BLOCK) {
            acc_one(__ldg(mrow + j), __ldg(arow + j), bestM, maxU);
        }

        // Warp reduction
        #pragma unroll
        for (int off = 16; off > 0; off >>= 1) {
            bestM = fmaxf(bestM, __shfl_xor_sync(0xffffffffu, bestM, off));
            maxU  = fmaxf(maxU,  __shfl_xor_sync(0xffffffffu, maxU,  off));
        }
        if (lane == 0) { sM[r][warp] = bestM; sU[r][warp] = maxU; }
    }

    __syncthreads();

    if (warp == 0 && lane < 2) {
        const int r   = lane;
        const int row = (r == 0) ? b : (NMENT - 1 - b);

        float bestM = fmaxf(fmaxf(sM[r][0], sM[r][1]), fmaxf(sM[r][2], sM[r][3]));
        float maxU  = fmaxf(fmaxf(sU[r][0], sU[r][1]), fmaxf(sU[r][2], sU[r][3]));

        const float nonana = __ldg(mask + (size_t)row * NMENT + row);   // diag
        const float e      = __ldg(eps_scores + row);
        if (nonana > 0.5f) bestM = fmaxf(bestM, e);

        const float row_cost = nonana * lc0 + (1.0f - nonana) * lc1;

        float loss = 0.0f;
        loss = fmaxf(loss, row_cost * (1.0f + maxU - bestM));   // -inf-safe
        const float dcost = (1.0f - nonana) * fnc;
        loss = fmaxf(loss, dcost * (1.0f + e - bestM));

        out[row] = loss;
    }
}

extern "C" void kernel_launch(void* const* d_in, const int* in_sizes, int n_in,
                              void* d_out, int out_size)
{
    const float* eps  = (const float*)d_in[0];
    const float* ana  = (const float*)d_in[1];
    const float* mask = (const float*)d_in[2];
    const float* lc   = (const float*)d_in[3];
    const float* fnc  = (const float*)d_in[4];
    float* out = (float*)d_out;

    mention_loss_kernel<<<NMENT / 2, BLOCK>>>(eps, ana, mask, lc, fnc, out);
}

// round 12
// speedup vs baseline: 1.0021x; 1.0021x over previous
#include <cuda_runtime.h>
#include <math_constants.h>

// N=4096 mention-ranking loss, one streaming pass.
// QUAD-row CTAs: CTA b in [0,1024) handles rows {b, 2047-b, 2048+b, 4095-b};
// per-CTA element count = 8190 for EVERY b -> perfectly uniform work.
// 1024 CTAs x 256 threads, 7 CTAs/SM -> whole grid in ONE resident wave at
// 56 warps/SM. Inner loop = R3's proven geometry: float4 mask (16B-aligned
// rows) + 4 scalar ana loads at 16B lane stride, unroll 2.

#define NMENT 4096
#define BLOCK 256

__device__ __forceinline__ void acc_one(float m, float s, float& bestM, float& maxU)
{
    if (m > 0.5f) bestM = fmaxf(bestM, s);
    else          maxU  = fmaxf(maxU,  s);
}

__device__ __forceinline__ void acc_g4(const float4 m, const float* __restrict__ a,
                                       int j, float& bestM, float& maxU)
{
    const float s0 = __ldg(a + j + 0);
    const float s1 = __ldg(a + j + 1);
    const float s2 = __ldg(a + j + 2);
    const float s3 = __ldg(a + j + 3);
    acc_one(m.x, s0, bestM, maxU);
    acc_one(m.y, s1, bestM, maxU);
    acc_one(m.z, s2, bestM, maxU);
    acc_one(m.w, s3, bestM, maxU);
}

__global__ __launch_bounds__(BLOCK, 7)
void mention_loss_kernel(const float* __restrict__ eps_scores,
                         const float* __restrict__ ana_scores,
                         const float* __restrict__ mask,
                         const float* __restrict__ link_costs,
                         const float* __restrict__ false_new_cost,
                         float* __restrict__ out)
{
    const int b    = (int)blockIdx.x;        // 0..1023
    const int tid  = (int)threadIdx.x;
    const int warp = tid >> 5;
    const int lane = tid & 31;

    int rows[4];
    rows[0] = b;
    rows[1] = 2047 - b;
    rows[2] = 2048 + b;
    rows[3] = 4095 - b;

    __shared__ float sM[4][BLOCK / 32];
    __shared__ float sU[4][BLOCK / 32];

    #pragma unroll
    for (int r = 0; r < 4; ++r) {
        const int row = rows[r];

        const float* __restrict__ mrow = mask + (size_t)row * NMENT;   // 16B-aligned
        const long long abase = ((long long)row * (row - 1)) >> 1;
        const float* __restrict__ arow = ana_scores + abase;

        float bestM = -CUDART_INF_F;
        float maxU  = -CUDART_INF_F;

        const int nv = row >> 2;               // full float4 groups
        const float4* __restrict__ mrow4 = (const float4*)mrow;

        int v = tid;
        for (; v + BLOCK < nv; v += 2 * BLOCK) {
            const float4 qa = __ldg(mrow4 + v);
            const float4 qb = __ldg(mrow4 + v + BLOCK);
            acc_g4(qa, arow, v << 2,           bestM, maxU);
            acc_g4(qb, arow, (v + BLOCK) << 2, bestM, maxU);
        }
        for (; v < nv; v += BLOCK) {
            const float4 qa = __ldg(mrow4 + v);
            acc_g4(qa, arow, v << 2, bestM, maxU);
        }
        // Scalar tail: j in [nv*4, row)
        for (int j = (nv << 2) + tid; j < row; j += BLOCK) {
            acc_one(__ldg(mrow + j), __ldg(arow + j), bestM, maxU);
        }

        // Warp reduction
        #pragma unroll
        for (int off = 16; off > 0; off >>= 1) {
            bestM = fmaxf(bestM, __shfl_xor_sync(0xffffffffu, bestM, off));
            maxU  = fmaxf(maxU,  __shfl_xor_sync(0xffffffffu, maxU,  off));
        }
        if (lane == 0) { sM[r][warp] = bestM; sU[r][warp] = maxU; }
    }

    __syncthreads();

    // Threads 0..3 finalize the four rows (8 partials each).
    if (tid < 4) {
        const int row = rows[tid];

        float bestM = -CUDART_INF_F;
        float maxU  = -CUDART_INF_F;
        #pragma unroll
        for (int w = 0; w < BLOCK / 32; ++w) {
            bestM = fmaxf(bestM, sM[tid][w]);
            maxU  = fmaxf(maxU,  sU[tid][w]);
        }

        const float nonana = __ldg(mask + (size_t)row * NMENT + row);   // diag
        const float e      = __ldg(eps_scores + row);
        if (nonana > 0.5f) bestM = fmaxf(bestM, e);

        const float lc0 = __ldg(link_costs + 0);    // false_link
        const float lc1 = __ldg(link_costs + 1);    // wrong_link
        const float fnc = __ldg(false_new_cost);

        const float row_cost = nonana * lc0 + (1.0f - nonana) * lc1;

        float loss = 0.0f;
        loss = fmaxf(loss, row_cost * (1.0f + maxU - bestM));   // -inf-safe
        const float dcost = (1.0f - nonana) * fnc;
        loss = fmaxf(loss, dcost * (1.0f + e - bestM));

        out[row] = loss;
    }
}

extern "C" void kernel_launch(void* const* d_in, const int* in_sizes, int n_in,
                              void* d_out, int out_size)
{
    const float* eps  = (const float*)d_in[0];
    const float* ana  = (const float*)d_in[1];
    const float* mask = (const float*)d_in[2];
    const float* lc   = (const float*)d_in[3];
    const float* fnc  = (const float*)d_in[4];
    float* out = (float*)d_out;

    mention_loss_kernel<<<NMENT / 4, BLOCK>>>(eps, ana, mask, lc, fnc, out);
}

// round 13
// speedup vs baseline: 1.1830x; 1.1805x over previous
#include <cuda_runtime.h>
#include <math_constants.h>

// N = 4096 mention-ranking loss, one streaming pass, row-paired CTAs.
// EXACT R3 winning configuration (2048 CTAs x 128 thr, occ 14, float4 mask +
// 16B-lane-stride scalar ana) with the main loop deepened to 4 groups/iter
// (20 loads in flight per thread vs 10) for higher MLP_eff.

#define NMENT 4096
#define BLOCK 128

__device__ __forceinline__ void acc_one(float m, float s, float& bestM, float& maxU)
{
    if (m > 0.5f) bestM = fmaxf(bestM, s);
    else          maxU  = fmaxf(maxU,  s);
}

__device__ __forceinline__ void acc_g4(const float4 m, const float* __restrict__ a,
                                       int j, float& bestM, float& maxU)
{
    const float s0 = __ldg(a + j + 0);
    const float s1 = __ldg(a + j + 1);
    const float s2 = __ldg(a + j + 2);
    const float s3 = __ldg(a + j + 3);
    acc_one(m.x, s0, bestM, maxU);
    acc_one(m.y, s1, bestM, maxU);
    acc_one(m.z, s2, bestM, maxU);
    acc_one(m.w, s3, bestM, maxU);
}

__global__ __launch_bounds__(BLOCK, 14)
void mention_loss_kernel(const float* __restrict__ eps_scores,
                         const float* __restrict__ ana_scores,
                         const float* __restrict__ mask,
                         const float* __restrict__ link_costs,
                         const float* __restrict__ false_new_cost,
                         float* __restrict__ out)
{
    const int b    = (int)blockIdx.x;        // 0..2047
    const int tid  = (int)threadIdx.x;
    const int warp = tid >> 5;
    const int lane = tid & 31;

    __shared__ float sM[2][BLOCK / 32];
    __shared__ float sU[2][BLOCK / 32];

    const float lc0 = __ldg(link_costs + 0);    // false_link
    const float lc1 = __ldg(link_costs + 1);    // wrong_link
    const float fnc = __ldg(false_new_cost);

    #pragma unroll
    for (int r = 0; r < 2; ++r) {
        const int row = (r == 0) ? b : (NMENT - 1 - b);

        const float* __restrict__ mrow = mask + (size_t)row * NMENT;   // 16B-aligned
        const long long abase = ((long long)row * (row - 1)) >> 1;
        const float* __restrict__ arow = ana_scores + abase;

        float bestM = -CUDART_INF_F;
        float maxU  = -CUDART_INF_F;

        const int nv = row >> 2;               // full float4 groups
        const float4* __restrict__ mrow4 = (const float4*)mrow;

        int v = tid;
        // 4-group deep main loop: 4 x LDG.128 + 16 x LDG.32 in flight.
        for (; v + 3 * BLOCK < nv; v += 4 * BLOCK) {
            const float4 q0 = __ldg(mrow4 + v);
            const float4 q1 = __ldg(mrow4 + v + BLOCK);
            const float4 q2 = __ldg(mrow4 + v + 2 * BLOCK);
            const float4 q3 = __ldg(mrow4 + v + 3 * BLOCK);
            acc_g4(q0, arow, v << 2,                 bestM, maxU);
            acc_g4(q1, arow, (v + BLOCK) << 2,       bestM, maxU);
            acc_g4(q2, arow, (v + 2 * BLOCK) << 2,   bestM, maxU);
            acc_g4(q3, arow, (v + 3 * BLOCK) << 2,   bestM, maxU);
        }
        for (; v < nv; v += BLOCK) {
            const float4 q0 = __ldg(mrow4 + v);
            acc_g4(q0, arow, v << 2, bestM, maxU);
        }
        // Scalar tail: j in [nv*4, row)
        for (int j = (nv << 2) + tid; j < row; j += BLOCK) {
            acc_one(__ldg(mrow + j), __ldg(arow + j), bestM, maxU);
        }

        // Warp reduction
        #pragma unroll
        for (int off = 16; off > 0; off >>= 1) {
            bestM = fmaxf(bestM, __shfl_xor_sync(0xffffffffu, bestM, off));
            maxU  = fmaxf(maxU,  __shfl_xor_sync(0xffffffffu, maxU,  off));
        }
        if (lane == 0) { sM[r][warp] = bestM; sU[r][warp] = maxU; }
    }

    __syncthreads();

    // One warp finalizes both rows (4 partials each).
    if (warp == 0 && lane < 2) {
        const int r   = lane;
        const int row = (r == 0) ? b : (NMENT - 1 - b);

        float bestM = fmaxf(fmaxf(sM[r][0], sM[r][1]), fmaxf(sM[r][2], sM[r][3]));
        float maxU  = fmaxf(fmaxf(sU[r][0], sU[r][1]), fmaxf(sU[r][2], sU[r][3]));

        const float nonana = __ldg(mask + (size_t)row * NMENT + row);   // diag
        const float e      = __ldg(eps_scores + row);
        if (nonana > 0.5f) bestM = fmaxf(bestM, e);

        const float row_cost = nonana * lc0 + (1.0f - nonana) * lc1;

        float loss = 0.0f;
        loss = fmaxf(loss, row_cost * (1.0f + maxU - bestM));   // -inf-safe
        const float dcost = (1.0f - nonana) * fnc;
        loss = fmaxf(loss, dcost * (1.0f + e - bestM));

        out[row] = loss;
    }
}

extern "C" void kernel_launch(void* const* d_in, const int* in_sizes, int n_in,
                              void* d_out, int out_size)
{
    const float* eps  = (const float*)d_in[0];
    const float* ana  = (const float*)d_in[1];
    const float* mask = (const float*)d_in[2];
    const float* lc   = (const float*)d_in[3];
    const float* fnc  = (const float*)d_in[4];
    float* out = (float*)d_out;

    mention_loss_kernel<<<NMENT / 2, BLOCK>>>(eps, ana, mask, lc, fnc, out);
}